// round 1
// baseline (speedup 1.0000x reference)
#include <cuda_runtime.h>
#include <math.h>

#define NF   24
#define FS   8
#define DY   32
#define DX   32
#define SEQL 300
#define TOTAL (NF*FS*DY*DX*SEQL)   // 58,982,400
#define N4    (TOTAL/4)            // 14,745,600
#define ROW4  (SEQL/4)             // 75

// token selected: s==2 || s==3 || (9 <= s <= 108)
#define SEL(s) ((s)==2 || (s)==3 || ((s)>=9 && (s)<=108))

__device__ float g_max;                 // global max of input (float bits, set via int atomicMax)
__device__ float g_patch[NF][16][10];   // normalized gaussian patch per frame
__device__ int   g_left[NF];
__device__ int   g_wid[NF];

__constant__ double c_lefts[NF] = {
    0.05, 0.0717, 0.0935, 0.1152, 0.137, 0.1587, 0.1804, 0.2022,
    0.2239, 0.2457, 0.2674, 0.2891, 0.3109, 0.3326, 0.3543, 0.3761,
    0.3978, 0.4196, 0.4413, 0.463, 0.4848, 0.5065, 0.5283, 0.55
};

// One block per frame: compute bbox (matching Python int()/round() semantics in
// double) and the normalized gaussian patch. Block 0 thread 0 resets g_max.
__global__ void init_kernel() {
    int f   = blockIdx.x;
    int tid = threadIdx.x;
    if (f == 0 && tid == 0) g_max = __int_as_float(0xFF800000); // -inf

    double l = c_lefts[f];
    double r = rint((l + 0.3) * 10000.0) / 10000.0;   // Python round(l+0.3, 4)
    int left  = (int)((double)DX * l);
    int right = (int)((double)DX * r);
    int w = right - left;
    int top    = (int)((double)DY * 0.25);   // 8
    int bottom = (int)((double)DY * 0.75);   // 24
    int h = bottom - top;                    // 16
    if (tid == 0) { g_left[f] = left; g_wid[f] = w; }

    __shared__ float s_val[160];
    __shared__ float s_max;
    int i = tid / 10, j = tid % 10;
    float v = 0.f;
    if (tid < 160) {
        if (j < w) {
            // jnp.linspace(0, h, h): step h/(h-1)
            float x  = (float)i * ((float)h / (float)(h - 1));
            float y  = (float)j * ((float)w / (float)(w - 1));
            float sx = (float)h / 3.0f;
            float sy = (float)w / 3.0f;
            float dx = x - (float)(h / 2);
            float dy = y - (float)(w / 2);
            v = expf(-(dx * dx / (2.f * sx * sx) + dy * dy / (2.f * sy * sy)));
        }
        s_val[tid] = v;
    }
    __syncthreads();
    if (tid == 0) {
        float m = 0.f;
        #pragma unroll 8
        for (int k = 0; k < 160; k++) m = fmaxf(m, s_val[k]);
        s_max = m;
    }
    __syncthreads();
    if (tid < 160) g_patch[f][i][j] = (j < w) ? (s_val[tid] / s_max) : 0.f;
}

// Pass A: fused streaming pass.
//   out = in * (selected(seq) ? 0.918 : 1.0)  for every element
//   + grid-wide max reduction of the input.
// Bbox-selected elements get overwritten by pass B.
__global__ void __launch_bounds__(512)
apply_weaken_max(const float4* __restrict__ in, float4* __restrict__ out) {
    const int stride = gridDim.x * blockDim.x;
    float mx = __int_as_float(0xFF800000);
    for (int i = blockIdx.x * blockDim.x + threadIdx.x; i < N4; i += stride) {
        float4 v = in[i];
        mx = fmaxf(mx, fmaxf(fmaxf(v.x, v.y), fmaxf(v.z, v.w)));
        int s0 = (i % ROW4) * 4;   // seq index of lane .x (rows are 4-aligned)
        float4 o;
        o.x = SEL(s0    ) ? v.x * 0.918f : v.x;
        o.y = SEL(s0 + 1) ? v.y * 0.918f : v.y;
        o.z = SEL(s0 + 2) ? v.z * 0.918f : v.z;
        o.w = SEL(s0 + 3) ? v.w * 0.918f : v.w;
        out[i] = o;
    }
    // warp reduce
    #pragma unroll
    for (int off = 16; off; off >>= 1)
        mx = fmaxf(mx, __shfl_xor_sync(0xffffffffu, mx, off));
    __shared__ float sm[16];
    if ((threadIdx.x & 31) == 0) sm[threadIdx.x >> 5] = mx;
    __syncthreads();
    if (threadIdx.x < 16) {
        mx = sm[threadIdx.x];
        #pragma unroll
        for (int off = 8; off; off >>= 1)
            mx = fmaxf(mx, __shfl_xor_sync(0xffffu, mx, off));
        if (threadIdx.x == 0)
            atomicMax((int*)&g_max, __float_as_int(mx));   // input >= 0
    }
}

// Pass B: only bbox rows x selected tokens (~3M elems).
// out = (wm != 0) ? in + 0.125*wm : in*0.918, wm = patch * max * INJECTION_SCALE
__global__ void __launch_bounds__(128)
apply_strengthen(const float* __restrict__ in, float* __restrict__ out) {
    int rid  = blockIdx.x;          // [0, NF*FS*16*10)
    int xoff = rid % 10;  rid /= 10;
    int yrow = rid % 16;  rid /= 16;
    int fs   = rid % FS;  rid /= FS;
    int f    = rid;
    int w = g_wid[f];
    if (xoff >= w) return;
    int x = g_left[f] + xoff;
    int y = 8 + yrow;

    float scale = g_max;            // INJECTION_SCALE = 1.0
    float wm = g_patch[f][yrow][xoff] * scale;

    int base = (((f * FS + fs) * DY + y) * DX + x) * SEQL;
    int tid = threadIdx.x;
    if (tid >= 102) return;
    int tok = (tid < 2) ? (tid + 2) : (tid + 7);   // {2,3} then 9..108
    float v = in[base + tok];
    out[base + tok] = (wm != 0.f) ? (v + 0.125f * wm) : (v * 0.918f);
}

extern "C" void kernel_launch(void* const* d_in, const int* in_sizes, int n_in,
                              void* d_out, int out_size) {
    const float* in = (const float*)d_in[0];
    float* out = (float*)d_out;

    init_kernel<<<NF, 192>>>();
    apply_weaken_max<<<608, 512>>>((const float4*)in, (float4*)out);
    apply_strengthen<<<NF * FS * 16 * 10, 128>>>(in, out);
}